// round 9
// baseline (speedup 1.0000x reference)
#include <cuda_runtime.h>
#include <cuda_bf16.h>
#include <math.h>
#include <stdint.h>

#define S_LEN 2048
#define HIDDEN 2048
#define NH 32
#define NKV 8
#define HD 64
#define KV_W (NKV*HD)   // 512

// ---------------------------------------------------------------------------
// Device-global scratch
// ---------------------------------------------------------------------------
__device__ __nv_bfloat16 g_Xh[S_LEN * HIDDEN],   g_Xl[S_LEN * HIDDEN];
__device__ __nv_bfloat16 g_Wqh[HIDDEN * HIDDEN], g_Wql[HIDDEN * HIDDEN];
__device__ __nv_bfloat16 g_Wkh[KV_W * HIDDEN],   g_Wkl[KV_W * HIDDEN];
__device__ __nv_bfloat16 g_Wvh[KV_W * HIDDEN],   g_Wvl[KV_W * HIDDEN];
__device__ __nv_bfloat16 g_Woh[HIDDEN * HIDDEN], g_Wol[HIDDEN * HIDDEN];

__device__ __nv_bfloat16 g_qh[S_LEN * HIDDEN], g_ql[S_LEN * HIDDEN];
__device__ __nv_bfloat16 g_kh[S_LEN * KV_W],   g_kl[S_LEN * KV_W];
__device__ __nv_bfloat16 g_vh[S_LEN * KV_W],   g_vl[S_LEN * KV_W];
__device__ __nv_bfloat16 g_Ath[S_LEN * HIDDEN], g_Atl[S_LEN * HIDDEN];

// ---------------------------------------------------------------------------
// mma.sync helpers
// ---------------------------------------------------------------------------
__device__ __forceinline__ uint32_t smem_u32(const void* p) {
    uint32_t a;
    asm("{ .reg .u64 t; cvta.to.shared.u64 t, %1; cvt.u32.u64 %0, t; }"
        : "=r"(a) : "l"(p));
    return a;
}
__device__ __forceinline__ void ldm_x4(uint32_t* r, uint32_t addr) {
    asm volatile("ldmatrix.sync.aligned.m8n8.x4.shared.b16 {%0,%1,%2,%3}, [%4];"
                 : "=r"(r[0]), "=r"(r[1]), "=r"(r[2]), "=r"(r[3]) : "r"(addr));
}
__device__ __forceinline__ void ldm_x2(uint32_t* r, uint32_t addr) {
    asm volatile("ldmatrix.sync.aligned.m8n8.x2.shared.b16 {%0,%1}, [%2];"
                 : "=r"(r[0]), "=r"(r[1]) : "r"(addr));
}
__device__ __forceinline__ void ldm_x2t(uint32_t* r, uint32_t addr) {
    asm volatile("ldmatrix.sync.aligned.m8n8.x2.trans.shared.b16 {%0,%1}, [%2];"
                 : "=r"(r[0]), "=r"(r[1]) : "r"(addr));
}
__device__ __forceinline__ void mma_bf16(float* d, const uint32_t* a, const uint32_t* b) {
    asm volatile(
        "mma.sync.aligned.m16n8k16.row.col.f32.bf16.bf16.f32 "
        "{%0,%1,%2,%3}, {%4,%5,%6,%7}, {%8,%9}, {%0,%1,%2,%3};"
        : "+f"(d[0]), "+f"(d[1]), "+f"(d[2]), "+f"(d[3])
        : "r"(a[0]), "r"(a[1]), "r"(a[2]), "r"(a[3]), "r"(b[0]), "r"(b[1]));
}
__device__ __forceinline__ void cp16(uint32_t saddr, const void* g) {
    asm volatile("cp.async.cg.shared.global [%0], [%1], 16;"
                 :: "r"(saddr), "l"(g) : "memory");
}

// ---------------------------------------------------------------------------
// fp32 -> bf16 hi/lo split conversion
// ---------------------------------------------------------------------------
__global__ __launch_bounds__(256) void cvt_split(
    const float* __restrict__ x, __nv_bfloat16* __restrict__ hi,
    __nv_bfloat16* __restrict__ lo, int n)
{
    int i = (blockIdx.x * 256 + threadIdx.x) * 4;
    if (i >= n) return;
    float4 v = *(const float4*)(x + i);
    __nv_bfloat16 h0 = __float2bfloat16(v.x), h1 = __float2bfloat16(v.y);
    __nv_bfloat16 h2 = __float2bfloat16(v.z), h3 = __float2bfloat16(v.w);
    __nv_bfloat16 l0 = __float2bfloat16(v.x - __bfloat162float(h0));
    __nv_bfloat16 l1 = __float2bfloat16(v.y - __bfloat162float(h1));
    __nv_bfloat16 l2 = __float2bfloat16(v.z - __bfloat162float(h2));
    __nv_bfloat16 l3 = __float2bfloat16(v.w - __bfloat162float(h3));
    __nv_bfloat162* hp = (__nv_bfloat162*)(hi + i);
    __nv_bfloat162* lp = (__nv_bfloat162*)(lo + i);
    hp[0] = __halves2bfloat162(h0, h1);
    hp[1] = __halves2bfloat162(h2, h3);
    lp[0] = __halves2bfloat162(l0, l1);
    lp[1] = __halves2bfloat162(l2, l3);
}

// ---------------------------------------------------------------------------
// Pipelined GEMM mainloop: BK=32, 3-stage cp.async, 2 CTAs/SM.
// Tile = 128 rows x 64 B; swizzle: chunk c of row r at (c ^ ((r>>1)&3)).
// Conflict-free for cp.async stores and all ldmatrix phases (enumerated).
// ---------------------------------------------------------------------------
#define TILEB 8192
#define STAGEB 32768
#define GEMM_SMEM (3 * STAGEB)   // 98304 B -> 2 CTAs/SM

extern __shared__ char dyn_smem[];

__device__ __forceinline__ void gemm_core(
    const __nv_bfloat16* __restrict__ gA0, const __nv_bfloat16* __restrict__ gA1,
    const __nv_bfloat16* __restrict__ gB0, const __nv_bfloat16* __restrict__ gB1,
    int K, uint32_t smb, float (&acc)[4][4][4])
{
    const int tid = threadIdx.x;
    const int wid = tid >> 5;
    const int lane = tid & 31;
    const int wm = wid >> 2;
    const int wn = wid & 3;

    const __nv_bfloat16* gT[4] = { gA0, gA1, gB0, gB1 };
    const int ldRow = tid >> 2;          // 0..63 (+64 with p)
    const int ldC   = tid & 3;           // 16B chunk 0..3
    const int nk = K / 32;

    auto issue = [&](int kc, int stg) {
        uint32_t sb = smb + stg * STAGEB;
#pragma unroll
        for (int t = 0; t < 4; t++) {
#pragma unroll
            for (int p = 0; p < 2; p++) {
                int row = ldRow + p * 64;
                int sw = ldC ^ ((row >> 1) & 3);
                cp16(sb + t * TILEB + row * 64 + sw * 16,
                     gT[t] + (size_t)row * K + kc * 32 + ldC * 8);
            }
        }
        asm volatile("cp.async.commit_group;" ::: "memory");
    };

    issue(0, 0);
    issue(1, 1);

    for (int kc = 0; kc < nk; kc++) {
        if (kc + 1 < nk)
            asm volatile("cp.async.wait_group 1;" ::: "memory");
        else
            asm volatile("cp.async.wait_group 0;" ::: "memory");
        __syncthreads();
        if (kc + 2 < nk) issue(kc + 2, (kc + 2) % 3);

        const uint32_t sb = smb + (kc % 3) * STAGEB;
#pragma unroll
        for (int ks = 0; ks < 2; ks++) {
            uint32_t bH[4][2], bL[4][2];
#pragma unroll
            for (int nt = 0; nt < 4; nt++) {
                int row = wn * 32 + nt * 8 + (lane & 7);
                int ch = ks * 2 + ((lane >> 3) & 1);
                uint32_t ba = sb + 2 * TILEB + row * 64
                            + ((ch ^ ((row >> 1) & 3)) * 16);
                ldm_x2(bH[nt], ba);
                ldm_x2(bL[nt], ba + TILEB);
            }
#pragma unroll
            for (int mt = 0; mt < 4; mt++) {
                int row = wm * 64 + mt * 16 + (lane & 15);
                int ch = ks * 2 + ((lane >> 4) & 1);
                uint32_t aa = sb + row * 64 + ((ch ^ ((row >> 1) & 3)) * 16);
                uint32_t aH[4], aL[4];
                ldm_x4(aH, aa);
                ldm_x4(aL, aa + TILEB);
#pragma unroll
                for (int nt = 0; nt < 4; nt++) mma_bf16(acc[mt][nt], aH, bH[nt]);
#pragma unroll
                for (int nt = 0; nt < 4; nt++) mma_bf16(acc[mt][nt], aL, bH[nt]);
#pragma unroll
                for (int nt = 0; nt < 4; nt++) mma_bf16(acc[mt][nt], aH, bL[nt]);
            }
        }
    }
}

__device__ __forceinline__ void epi_split(
    float (&acc)[4][4][4], __nv_bfloat16* Ch, __nv_bfloat16* Cl,
    int r0, int c0, int N)
{
    const int lane = threadIdx.x & 31;
    const int wid = threadIdx.x >> 5;
    const int wm = wid >> 2, wn = wid & 3;
    const int cr = lane >> 2;
    const int cc = (lane & 3) * 2;
#pragma unroll
    for (int mt = 0; mt < 4; mt++) {
#pragma unroll
        for (int nt = 0; nt < 4; nt++) {
            size_t i0 = (size_t)(r0 + wm * 64 + mt * 16 + cr) * N
                      + c0 + wn * 32 + nt * 8 + cc;
            size_t i1 = i0 + 8 * (size_t)N;
#pragma unroll
            for (int half = 0; half < 2; half++) {
                size_t ix = half ? i1 : i0;
                float e0 = acc[mt][nt][half * 2 + 0];
                float e1 = acc[mt][nt][half * 2 + 1];
                __nv_bfloat16 h0 = __float2bfloat16(e0);
                __nv_bfloat16 h1 = __float2bfloat16(e1);
                __nv_bfloat162 hp = __halves2bfloat162(h0, h1);
                __nv_bfloat162 lp = __halves2bfloat162(
                    __float2bfloat16(e0 - __bfloat162float(h0)),
                    __float2bfloat16(e1 - __bfloat162float(h1)));
                *(uint32_t*)(Ch + ix) = *reinterpret_cast<uint32_t*>(&hp);
                *(uint32_t*)(Cl + ix) = *reinterpret_cast<uint32_t*>(&lp);
            }
        }
    }
}

__global__ __launch_bounds__(256, 2) void gemm_qkv()
{
    const uint32_t smb = smem_u32(dyn_smem);
    const int bx = blockIdx.x;
    const int r0 = blockIdx.y * 128;

    const __nv_bfloat16 *Bh, *Bl;
    __nv_bfloat16 *Ch, *Cl;
    int N, c0;
    if (bx < 16)      { Bh = g_Wqh; Bl = g_Wql; Ch = g_qh; Cl = g_ql; N = HIDDEN; c0 = bx * 128; }
    else if (bx < 20) { Bh = g_Wkh; Bl = g_Wkl; Ch = g_kh; Cl = g_kl; N = KV_W;  c0 = (bx - 16) * 128; }
    else              { Bh = g_Wvh; Bl = g_Wvl; Ch = g_vh; Cl = g_vl; N = KV_W;  c0 = (bx - 20) * 128; }

    float acc[4][4][4];
#pragma unroll
    for (int i = 0; i < 4; i++)
#pragma unroll
        for (int j = 0; j < 4; j++)
#pragma unroll
            for (int e = 0; e < 4; e++) acc[i][j][e] = 0.f;

    gemm_core(g_Xh + (size_t)r0 * HIDDEN, g_Xl + (size_t)r0 * HIDDEN,
              Bh + (size_t)c0 * HIDDEN, Bl + (size_t)c0 * HIDDEN,
              HIDDEN, smb, acc);
    epi_split(acc, Ch, Cl, r0, c0, N);
}

__global__ __launch_bounds__(256, 2) void gemm_oproj(float* __restrict__ Cf)
{
    const uint32_t smb = smem_u32(dyn_smem);
    const int r0 = blockIdx.y * 128;
    const int c0 = blockIdx.x * 128;

    float acc[4][4][4];
#pragma unroll
    for (int i = 0; i < 4; i++)
#pragma unroll
        for (int j = 0; j < 4; j++)
#pragma unroll
            for (int e = 0; e < 4; e++) acc[i][j][e] = 0.f;

    gemm_core(g_Ath + (size_t)r0 * HIDDEN, g_Atl + (size_t)r0 * HIDDEN,
              g_Woh + (size_t)c0 * HIDDEN, g_Wol + (size_t)c0 * HIDDEN,
              HIDDEN, smb, acc);

    const int lane = threadIdx.x & 31;
    const int wid = threadIdx.x >> 5;
    const int wm = wid >> 2, wn = wid & 3;
    const int cr = lane >> 2;
    const int cc = (lane & 3) * 2;
#pragma unroll
    for (int mt = 0; mt < 4; mt++) {
#pragma unroll
        for (int nt = 0; nt < 4; nt++) {
            float* base = Cf + (size_t)(r0 + wm * 64 + mt * 16 + cr) * HIDDEN
                             + c0 + wn * 32 + nt * 8 + cc;
            *(float2*)base = make_float2(acc[mt][nt][0], acc[mt][nt][1]);
            *(float2*)(base + 8 * (size_t)HIDDEN) =
                make_float2(acc[mt][nt][2], acc[mt][nt][3]);
        }
    }
}

// ---------------------------------------------------------------------------
// Flash attention on mma.sync (exact R7 version — known-good 215 us)
// ---------------------------------------------------------------------------
#define SROW 72
#define AQH 0
#define AQL 9216
#define AKH 18432
#define AKL 23040
#define AVH 27648
#define AVL 32256
#define FA_SMEM (36864 * 2)

__global__ __launch_bounds__(256) void flash_attn_mma(
    const __nv_bfloat16* __restrict__ Qh_g, const __nv_bfloat16* __restrict__ Ql_g,
    const __nv_bfloat16* __restrict__ Kh_g, const __nv_bfloat16* __restrict__ Kl_g,
    const __nv_bfloat16* __restrict__ Vh_g, const __nv_bfloat16* __restrict__ Vl_g,
    __nv_bfloat16* __restrict__ Oh_g, __nv_bfloat16* __restrict__ Ol_g)
{
    __nv_bfloat16* sm = (__nv_bfloat16*)dyn_smem;
    const uint32_t smb = smem_u32(sm);

    const int tid  = threadIdx.x;
    const int wid  = tid >> 5;
    const int lane = tid & 31;
    const int qb = (int)gridDim.x - 1 - (int)blockIdx.x;
    const int hh = blockIdx.y;
    const int q0 = qb * 128;
    const int kvoff = (hh >> 2) * HD;

#pragma unroll
    for (int p = 0; p < 8; p++) {
        int idx = tid + p * 256;
        int t = idx >> 10;
        int rem = idx & 1023;
        int r = rem >> 3;
        int c = rem & 7;
        const __nv_bfloat16* src = (t ? Ql_g : Qh_g) +
            (size_t)(q0 + r) * HIDDEN + hh * HD + c * 8;
        uint4 d = *(const uint4*)src;
        *(uint4*)(sm + (t ? AQL : AQH) + r * SROW + c * 8) = d;
    }

    float o[8][4];
#pragma unroll
    for (int nt = 0; nt < 8; nt++)
#pragma unroll
        for (int e = 0; e < 4; e++) o[nt][e] = 0.f;
    float m0 = -1e30f, m1 = -1e30f, l0 = 0.f, l1 = 0.f;

    const int cr = lane >> 2;
    const int cc = (lane & 3) * 2;
    const int row0 = q0 + wid * 16 + cr;
    const int row1 = row0 + 8;

    const uint32_t aHq = smb + (uint32_t)(AQH +
        (wid * 16 + (lane & 15)) * SROW + ((lane >> 4) & 1) * 8) * 2;
    const uint32_t aLq = aHq + (uint32_t)(AQL - AQH) * 2;
    const uint32_t bK = smb + (uint32_t)(AKH +
        (lane & 7) * SROW + ((lane >> 3) & 1) * 8) * 2;
    const uint32_t bV = smb + (uint32_t)(AVH +
        ((lane & 7) + ((lane >> 3) & 1) * 8) * SROW) * 2;

    const int nkv = 2 * qb + 2;
    for (int jb = 0; jb < nkv; jb++) {
        const int k0 = jb * 64;
        __syncthreads();
#pragma unroll
        for (int p = 0; p < 8; p++) {
            int idx = tid + p * 256;
            int t = idx >> 9;
            int rem = idx & 511;
            int r = rem >> 3;
            int c = rem & 7;
            const __nv_bfloat16* src =
                (t == 0 ? Kh_g : t == 1 ? Kl_g : t == 2 ? Vh_g : Vl_g) +
                (size_t)(k0 + r) * KV_W + kvoff + c * 8;
            uint4 d = *(const uint4*)src;
            int dst = (t == 0 ? AKH : t == 1 ? AKL : t == 2 ? AVH : AVL);
            *(uint4*)(sm + dst + r * SROW + c * 8) = d;
        }
        __syncthreads();

        float s[8][4];
#pragma unroll
        for (int nt = 0; nt < 8; nt++)
#pragma unroll
            for (int e = 0; e < 4; e++) s[nt][e] = 0.f;

#pragma unroll
        for (int ks = 0; ks < 4; ks++) {
            uint32_t aH[4], aL[4];
            ldm_x4(aH, aHq + ks * 32);
            ldm_x4(aL, aLq + ks * 32);
#pragma unroll
            for (int nt = 0; nt < 8; nt++) {
                uint32_t bh[2], bl[2];
                uint32_t ba = bK + (uint32_t)(nt * 8 * SROW) * 2 + ks * 32;
                ldm_x2(bh, ba);
                ldm_x2(bl, ba + (uint32_t)(AKL - AKH) * 2);
                mma_bf16(s[nt], aH, bh);
                mma_bf16(s[nt], aL, bh);
                mma_bf16(s[nt], aH, bl);
            }
        }

        const bool need_mask = (k0 + 63 > q0);
#pragma unroll
        for (int nt = 0; nt < 8; nt++) {
            int col = k0 + nt * 8 + cc;
            s[nt][0] *= 0.125f; s[nt][1] *= 0.125f;
            s[nt][2] *= 0.125f; s[nt][3] *= 0.125f;
            if (need_mask) {
                if (col > row0)     s[nt][0] = -1e30f;
                if (col + 1 > row0) s[nt][1] = -1e30f;
                if (col > row1)     s[nt][2] = -1e30f;
                if (col + 1 > row1) s[nt][3] = -1e30f;
            }
        }

        float mx0 = -1e30f, mx1 = -1e30f;
#pragma unroll
        for (int nt = 0; nt < 8; nt++) {
            mx0 = fmaxf(mx0, fmaxf(s[nt][0], s[nt][1]));
            mx1 = fmaxf(mx1, fmaxf(s[nt][2], s[nt][3]));
        }
        mx0 = fmaxf(mx0, __shfl_xor_sync(0xffffffffu, mx0, 1));
        mx0 = fmaxf(mx0, __shfl_xor_sync(0xffffffffu, mx0, 2));
        mx1 = fmaxf(mx1, __shfl_xor_sync(0xffffffffu, mx1, 1));
        mx1 = fmaxf(mx1, __shfl_xor_sync(0xffffffffu, mx1, 2));

        float m0n = fmaxf(m0, mx0);
        float m1n = fmaxf(m1, mx1);

        float sum0 = 0.f, sum1 = 0.f;
#pragma unroll
        for (int nt = 0; nt < 8; nt++) {
            s[nt][0] = __expf(s[nt][0] - m0n);
            s[nt][1] = __expf(s[nt][1] - m0n);
            s[nt][2] = __expf(s[nt][2] - m1n);
            s[nt][3] = __expf(s[nt][3] - m1n);
            sum0 += s[nt][0] + s[nt][1];
            sum1 += s[nt][2] + s[nt][3];
        }
        sum0 += __shfl_xor_sync(0xffffffffu, sum0, 1);
        sum0 += __shfl_xor_sync(0xffffffffu, sum0, 2);
        sum1 += __shfl_xor_sync(0xffffffffu, sum1, 1);
        sum1 += __shfl_xor_sync(0xffffffffu, sum1, 2);

        float sc0 = __expf(m0 - m0n);
        float sc1 = __expf(m1 - m1n);
        l0 = l0 * sc0 + sum0;
        l1 = l1 * sc1 + sum1;
        m0 = m0n; m1 = m1n;

#pragma unroll
        for (int nt = 0; nt < 8; nt++) {
            o[nt][0] *= sc0; o[nt][1] *= sc0;
            o[nt][2] *= sc1; o[nt][3] *= sc1;
        }

#pragma unroll
        for (int ks = 0; ks < 4; ks++) {
            uint32_t aP[4], aPl[4];
#pragma unroll
            for (int half = 0; half < 2; half++) {
                int nt = 2 * ks + half;
#pragma unroll
                for (int rr = 0; rr < 2; rr++) {
                    float e0 = s[nt][rr * 2 + 0];
                    float e1 = s[nt][rr * 2 + 1];
                    __nv_bfloat16 h0 = __float2bfloat16(e0);
                    __nv_bfloat16 h1 = __float2bfloat16(e1);
                    float r0f = e0 - __bfloat162float(h0);
                    float r1f = e1 - __bfloat162float(h1);
                    __nv_bfloat162 hp = __halves2bfloat162(h0, h1);
                    __nv_bfloat162 lp = __halves2bfloat162(
                        __float2bfloat16(r0f), __float2bfloat16(r1f));
                    aP [half * 2 + rr] = *reinterpret_cast<uint32_t*>(&hp);
                    aPl[half * 2 + rr] = *reinterpret_cast<uint32_t*>(&lp);
                }
            }
#pragma unroll
            for (int nt = 0; nt < 8; nt++) {
                uint32_t bh[2], bl[2];
                uint32_t ba = bV + (uint32_t)(ks * 16 * SROW + nt * 8) * 2;
                ldm_x2t(bh, ba);
                ldm_x2t(bl, ba + (uint32_t)(AVL - AVH) * 2);
                mma_bf16(o[nt], aP,  bh);
                mma_bf16(o[nt], aPl, bh);
                mma_bf16(o[nt], aP,  bl);
            }
        }
    }

    float inv0 = 1.f / l0;
    float inv1 = 1.f / l1;
#pragma unroll
    for (int nt = 0; nt < 8; nt++) {
        size_t i0 = (size_t)row0 * HIDDEN + hh * HD + nt * 8 + cc;
        size_t i1 = (size_t)row1 * HIDDEN + hh * HD + nt * 8 + cc;
        float e0 = o[nt][0] * inv0, e1 = o[nt][1] * inv0;
        float e2 = o[nt][2] * inv1, e3 = o[nt][3] * inv1;
        __nv_bfloat16 h0 = __float2bfloat16(e0), h1 = __float2bfloat16(e1);
        __nv_bfloat16 h2 = __float2bfloat16(e2), h3 = __float2bfloat16(e3);
        __nv_bfloat162 hp0 = __halves2bfloat162(h0, h1);
        __nv_bfloat162 hp1 = __halves2bfloat162(h2, h3);
        __nv_bfloat162 lp0 = __halves2bfloat162(
            __float2bfloat16(e0 - __bfloat162float(h0)),
            __float2bfloat16(e1 - __bfloat162float(h1)));
        __nv_bfloat162 lp1 = __halves2bfloat162(
            __float2bfloat16(e2 - __bfloat162float(h2)),
            __float2bfloat16(e3 - __bfloat162float(h3)));
        *(uint32_t*)(Oh_g + i0) = *reinterpret_cast<uint32_t*>(&hp0);
        *(uint32_t*)(Oh_g + i1) = *reinterpret_cast<uint32_t*>(&hp1);
        *(uint32_t*)(Ol_g + i0) = *reinterpret_cast<uint32_t*>(&lp0);
        *(uint32_t*)(Ol_g + i1) = *reinterpret_cast<uint32_t*>(&lp1);
    }
}

// ---------------------------------------------------------------------------
// kernel_launch
// ---------------------------------------------------------------------------
extern "C" void kernel_launch(void* const* d_in, const int* in_sizes, int n_in,
                              void* d_out, int out_size)
{
    const float* X  = (const float*)d_in[0];
    const float* Wq = (const float*)d_in[2];
    const float* Wk = (const float*)d_in[3];
    const float* Wv = (const float*)d_in[4];
    const float* Wo = (const float*)d_in[5];
    float* out = (float*)d_out;

    __nv_bfloat16 *Xh, *Xl, *Wqh, *Wql, *Wkh, *Wkl, *Wvh, *Wvl, *Woh, *Wol;
    __nv_bfloat16 *qh, *ql, *kh, *kl, *vh, *vl, *Ath, *Atl;
    cudaGetSymbolAddress((void**)&Xh, g_Xh);   cudaGetSymbolAddress((void**)&Xl, g_Xl);
    cudaGetSymbolAddress((void**)&Wqh, g_Wqh); cudaGetSymbolAddress((void**)&Wql, g_Wql);
    cudaGetSymbolAddress((void**)&Wkh, g_Wkh); cudaGetSymbolAddress((void**)&Wkl, g_Wkl);
    cudaGetSymbolAddress((void**)&Wvh, g_Wvh); cudaGetSymbolAddress((void**)&Wvl, g_Wvl);
    cudaGetSymbolAddress((void**)&Woh, g_Woh); cudaGetSymbolAddress((void**)&Wol, g_Wol);
    cudaGetSymbolAddress((void**)&qh, g_qh);   cudaGetSymbolAddress((void**)&ql, g_ql);
    cudaGetSymbolAddress((void**)&kh, g_kh);   cudaGetSymbolAddress((void**)&kl, g_kl);
    cudaGetSymbolAddress((void**)&vh, g_vh);   cudaGetSymbolAddress((void**)&vl, g_vl);
    cudaGetSymbolAddress((void**)&Ath, g_Ath); cudaGetSymbolAddress((void**)&Atl, g_Atl);

    cvt_split<<<(S_LEN * HIDDEN) / 1024, 256>>>(X, Xh, Xl, S_LEN * HIDDEN);
    cvt_split<<<(HIDDEN * HIDDEN) / 1024, 256>>>(Wq, Wqh, Wql, HIDDEN * HIDDEN);
    cvt_split<<<(KV_W * HIDDEN) / 1024, 256>>>(Wk, Wkh, Wkl, KV_W * HIDDEN);
    cvt_split<<<(KV_W * HIDDEN) / 1024, 256>>>(Wv, Wvh, Wvl, KV_W * HIDDEN);
    cvt_split<<<(HIDDEN * HIDDEN) / 1024, 256>>>(Wo, Woh, Wol, HIDDEN * HIDDEN);

    cudaFuncSetAttribute(gemm_qkv, cudaFuncAttributeMaxDynamicSharedMemorySize, GEMM_SMEM);
    cudaFuncSetAttribute(gemm_oproj, cudaFuncAttributeMaxDynamicSharedMemorySize, GEMM_SMEM);

    gemm_qkv<<<dim3(24, 16), 256, GEMM_SMEM>>>();

    cudaFuncSetAttribute(flash_attn_mma, cudaFuncAttributeMaxDynamicSharedMemorySize, FA_SMEM);
    flash_attn_mma<<<dim3(S_LEN / 128, NH), 256, FA_SMEM>>>(
        qh, ql, kh, kl, vh, vl, Ath, Atl);

    gemm_oproj<<<dim3(16, 16), 256, GEMM_SMEM>>>(out);
}

// round 10
// speedup vs baseline: 1.0372x; 1.0372x over previous
#include <cuda_runtime.h>
#include <cuda_bf16.h>
#include <math.h>
#include <stdint.h>

#define S_LEN 2048
#define HIDDEN 2048
#define NH 32
#define NKV 8
#define HD 64
#define KV_W (NKV*HD)   // 512

// ---------------------------------------------------------------------------
// Device-global scratch
// ---------------------------------------------------------------------------
__device__ __nv_bfloat16 g_Xh[S_LEN * HIDDEN],   g_Xl[S_LEN * HIDDEN];
__device__ __nv_bfloat16 g_Wqh[HIDDEN * HIDDEN], g_Wql[HIDDEN * HIDDEN];
__device__ __nv_bfloat16 g_Wkh[KV_W * HIDDEN],   g_Wkl[KV_W * HIDDEN];
__device__ __nv_bfloat16 g_Wvh[KV_W * HIDDEN],   g_Wvl[KV_W * HIDDEN];
__device__ __nv_bfloat16 g_Woh[HIDDEN * HIDDEN], g_Wol[HIDDEN * HIDDEN];

__device__ __nv_bfloat16 g_qh[S_LEN * HIDDEN], g_ql[S_LEN * HIDDEN];
__device__ __nv_bfloat16 g_kh[S_LEN * KV_W],   g_kl[S_LEN * KV_W];
__device__ __nv_bfloat16 g_vh[S_LEN * KV_W],   g_vl[S_LEN * KV_W];
__device__ __nv_bfloat16 g_Ath[S_LEN * HIDDEN], g_Atl[S_LEN * HIDDEN];

// ---------------------------------------------------------------------------
// mma.sync helpers
// ---------------------------------------------------------------------------
__device__ __forceinline__ uint32_t smem_u32(const void* p) {
    uint32_t a;
    asm("{ .reg .u64 t; cvta.to.shared.u64 t, %1; cvt.u32.u64 %0, t; }"
        : "=r"(a) : "l"(p));
    return a;
}
__device__ __forceinline__ void ldm_x4(uint32_t* r, uint32_t addr) {
    asm volatile("ldmatrix.sync.aligned.m8n8.x4.shared.b16 {%0,%1,%2,%3}, [%4];"
                 : "=r"(r[0]), "=r"(r[1]), "=r"(r[2]), "=r"(r[3]) : "r"(addr));
}
__device__ __forceinline__ void ldm_x2(uint32_t* r, uint32_t addr) {
    asm volatile("ldmatrix.sync.aligned.m8n8.x2.shared.b16 {%0,%1}, [%2];"
                 : "=r"(r[0]), "=r"(r[1]) : "r"(addr));
}
__device__ __forceinline__ void ldm_x2t(uint32_t* r, uint32_t addr) {
    asm volatile("ldmatrix.sync.aligned.m8n8.x2.trans.shared.b16 {%0,%1}, [%2];"
                 : "=r"(r[0]), "=r"(r[1]) : "r"(addr));
}
__device__ __forceinline__ void mma_bf16(float* d, const uint32_t* a, const uint32_t* b) {
    asm volatile(
        "mma.sync.aligned.m16n8k16.row.col.f32.bf16.bf16.f32 "
        "{%0,%1,%2,%3}, {%4,%5,%6,%7}, {%8,%9}, {%0,%1,%2,%3};"
        : "+f"(d[0]), "+f"(d[1]), "+f"(d[2]), "+f"(d[3])
        : "r"(a[0]), "r"(a[1]), "r"(a[2]), "r"(a[3]), "r"(b[0]), "r"(b[1]));
}
__device__ __forceinline__ void cp16(uint32_t saddr, const void* g) {
    asm volatile("cp.async.cg.shared.global [%0], [%1], 16;"
                 :: "r"(saddr), "l"(g) : "memory");
}

// ---------------------------------------------------------------------------
// fp32 -> bf16 hi/lo split conversion
// ---------------------------------------------------------------------------
__global__ __launch_bounds__(256) void cvt_split(
    const float* __restrict__ x, __nv_bfloat16* __restrict__ hi,
    __nv_bfloat16* __restrict__ lo, int n)
{
    int i = (blockIdx.x * 256 + threadIdx.x) * 4;
    if (i >= n) return;
    float4 v = *(const float4*)(x + i);
    __nv_bfloat16 h0 = __float2bfloat16(v.x), h1 = __float2bfloat16(v.y);
    __nv_bfloat16 h2 = __float2bfloat16(v.z), h3 = __float2bfloat16(v.w);
    __nv_bfloat16 l0 = __float2bfloat16(v.x - __bfloat162float(h0));
    __nv_bfloat16 l1 = __float2bfloat16(v.y - __bfloat162float(h1));
    __nv_bfloat16 l2 = __float2bfloat16(v.z - __bfloat162float(h2));
    __nv_bfloat16 l3 = __float2bfloat16(v.w - __bfloat162float(h3));
    __nv_bfloat162* hp = (__nv_bfloat162*)(hi + i);
    __nv_bfloat162* lp = (__nv_bfloat162*)(lo + i);
    hp[0] = __halves2bfloat162(h0, h1);
    hp[1] = __halves2bfloat162(h2, h3);
    lp[0] = __halves2bfloat162(l0, l1);
    lp[1] = __halves2bfloat162(l2, l3);
}

// ---------------------------------------------------------------------------
// Pipelined GEMM mainloop (exact R7 config): BK=64, 3-stage cp.async,
// SW128 XOR swizzle, 1 CTA/SM.
// ---------------------------------------------------------------------------
#define TILEB 16384
#define STAGEB 65536
#define GEMM_SMEM (3 * STAGEB)

extern __shared__ char dyn_smem[];

__device__ __forceinline__ void gemm_core(
    const __nv_bfloat16* __restrict__ gA0, const __nv_bfloat16* __restrict__ gA1,
    const __nv_bfloat16* __restrict__ gB0, const __nv_bfloat16* __restrict__ gB1,
    int K, uint32_t smb, float (&acc)[4][4][4])
{
    const int tid = threadIdx.x;
    const int wid = tid >> 5;
    const int lane = tid & 31;
    const int wm = wid >> 2;
    const int wn = wid & 3;

    const __nv_bfloat16* gT[4] = { gA0, gA1, gB0, gB1 };
    const int ldRow = tid >> 3;
    const int ldC   = tid & 7;
    const int nk = K / 64;

    auto issue = [&](int kc, int stg) {
        uint32_t sb = smb + stg * STAGEB;
#pragma unroll
        for (int t = 0; t < 4; t++) {
#pragma unroll
            for (int p = 0; p < 4; p++) {
                int row = ldRow + p * 32;
                int sw = ldC ^ (row & 7);
                cp16(sb + t * TILEB + row * 128 + sw * 16,
                     gT[t] + (size_t)row * K + kc * 64 + ldC * 8);
            }
        }
        asm volatile("cp.async.commit_group;" ::: "memory");
    };

    issue(0, 0);
    issue(1, 1);

    for (int kc = 0; kc < nk; kc++) {
        if (kc + 1 < nk)
            asm volatile("cp.async.wait_group 1;" ::: "memory");
        else
            asm volatile("cp.async.wait_group 0;" ::: "memory");
        __syncthreads();
        if (kc + 2 < nk) issue(kc + 2, (kc + 2) % 3);

        const uint32_t sb = smb + (kc % 3) * STAGEB;
#pragma unroll
        for (int ks = 0; ks < 4; ks++) {
            uint32_t bH[4][2], bL[4][2];
#pragma unroll
            for (int nt = 0; nt < 4; nt++) {
                int row = wn * 32 + nt * 8 + (lane & 7);
                int ch = ks * 2 + ((lane >> 3) & 1);
                uint32_t ba = sb + 2 * TILEB + row * 128 + ((ch ^ (row & 7)) * 16);
                ldm_x2(bH[nt], ba);
                ldm_x2(bL[nt], ba + TILEB);
            }
#pragma unroll
            for (int mt = 0; mt < 4; mt++) {
                int row = wm * 64 + mt * 16 + (lane & 15);
                int ch = ks * 2 + ((lane >> 4) & 1);
                uint32_t aa = sb + row * 128 + ((ch ^ (row & 7)) * 16);
                uint32_t aH[4], aL[4];
                ldm_x4(aH, aa);
                ldm_x4(aL, aa + TILEB);
#pragma unroll
                for (int nt = 0; nt < 4; nt++) mma_bf16(acc[mt][nt], aH, bH[nt]);
#pragma unroll
                for (int nt = 0; nt < 4; nt++) mma_bf16(acc[mt][nt], aL, bH[nt]);
#pragma unroll
                for (int nt = 0; nt < 4; nt++) mma_bf16(acc[mt][nt], aH, bL[nt]);
            }
        }
    }
}

__device__ __forceinline__ void epi_split(
    float (&acc)[4][4][4], __nv_bfloat16* Ch, __nv_bfloat16* Cl,
    int r0, int c0, int N)
{
    const int lane = threadIdx.x & 31;
    const int wid = threadIdx.x >> 5;
    const int wm = wid >> 2, wn = wid & 3;
    const int cr = lane >> 2;
    const int cc = (lane & 3) * 2;
#pragma unroll
    for (int mt = 0; mt < 4; mt++) {
#pragma unroll
        for (int nt = 0; nt < 4; nt++) {
            size_t i0 = (size_t)(r0 + wm * 64 + mt * 16 + cr) * N
                      + c0 + wn * 32 + nt * 8 + cc;
            size_t i1 = i0 + 8 * (size_t)N;
#pragma unroll
            for (int half = 0; half < 2; half++) {
                size_t ix = half ? i1 : i0;
                float e0 = acc[mt][nt][half * 2 + 0];
                float e1 = acc[mt][nt][half * 2 + 1];
                __nv_bfloat16 h0 = __float2bfloat16(e0);
                __nv_bfloat16 h1 = __float2bfloat16(e1);
                __nv_bfloat162 hp = __halves2bfloat162(h0, h1);
                __nv_bfloat162 lp = __halves2bfloat162(
                    __float2bfloat16(e0 - __bfloat162float(h0)),
                    __float2bfloat16(e1 - __bfloat162float(h1)));
                *(uint32_t*)(Ch + ix) = *reinterpret_cast<uint32_t*>(&hp);
                *(uint32_t*)(Cl + ix) = *reinterpret_cast<uint32_t*>(&lp);
            }
        }
    }
}

__global__ __launch_bounds__(256, 1) void gemm_qkv()
{
    const uint32_t smb = smem_u32(dyn_smem);
    const int bx = blockIdx.x;
    const int r0 = blockIdx.y * 128;

    const __nv_bfloat16 *Bh, *Bl;
    __nv_bfloat16 *Ch, *Cl;
    int N, c0;
    if (bx < 16)      { Bh = g_Wqh; Bl = g_Wql; Ch = g_qh; Cl = g_ql; N = HIDDEN; c0 = bx * 128; }
    else if (bx < 20) { Bh = g_Wkh; Bl = g_Wkl; Ch = g_kh; Cl = g_kl; N = KV_W;  c0 = (bx - 16) * 128; }
    else              { Bh = g_Wvh; Bl = g_Wvl; Ch = g_vh; Cl = g_vl; N = KV_W;  c0 = (bx - 20) * 128; }

    float acc[4][4][4];
#pragma unroll
    for (int i = 0; i < 4; i++)
#pragma unroll
        for (int j = 0; j < 4; j++)
#pragma unroll
            for (int e = 0; e < 4; e++) acc[i][j][e] = 0.f;

    gemm_core(g_Xh + (size_t)r0 * HIDDEN, g_Xl + (size_t)r0 * HIDDEN,
              Bh + (size_t)c0 * HIDDEN, Bl + (size_t)c0 * HIDDEN,
              HIDDEN, smb, acc);
    epi_split(acc, Ch, Cl, r0, c0, N);
}

__global__ __launch_bounds__(256, 1) void gemm_oproj(float* __restrict__ Cf)
{
    const uint32_t smb = smem_u32(dyn_smem);
    const int r0 = blockIdx.y * 128;
    const int c0 = blockIdx.x * 128;

    float acc[4][4][4];
#pragma unroll
    for (int i = 0; i < 4; i++)
#pragma unroll
        for (int j = 0; j < 4; j++)
#pragma unroll
            for (int e = 0; e < 4; e++) acc[i][j][e] = 0.f;

    gemm_core(g_Ath + (size_t)r0 * HIDDEN, g_Atl + (size_t)r0 * HIDDEN,
              g_Woh + (size_t)c0 * HIDDEN, g_Wol + (size_t)c0 * HIDDEN,
              HIDDEN, smb, acc);

    const int lane = threadIdx.x & 31;
    const int wid = threadIdx.x >> 5;
    const int wm = wid >> 2, wn = wid & 3;
    const int cr = lane >> 2;
    const int cc = (lane & 3) * 2;
#pragma unroll
    for (int mt = 0; mt < 4; mt++) {
#pragma unroll
        for (int nt = 0; nt < 4; nt++) {
            float* base = Cf + (size_t)(r0 + wm * 64 + mt * 16 + cr) * HIDDEN
                             + c0 + wn * 32 + nt * 8 + cc;
            *(float2*)base = make_float2(acc[mt][nt][0], acc[mt][nt][1]);
            *(float2*)(base + 8 * (size_t)HIDDEN) =
                make_float2(acc[mt][nt][2], acc[mt][nt][3]);
        }
    }
}

// ---------------------------------------------------------------------------
// Flash attention on mma.sync — cp.async double-buffered K/V, 1 CTA/SM
// (full register budget; only the load pipeline differs from R7).
// smem (b16 elems): Q hi [0,9216), Q lo [9216,18432),
//   KV stage0 [18432, 36864), stage1 [36864, 55296).
// Stage layout: Kh(4608) Kl(4608) Vh(4608) Vl(4608); rows 72 b16 (144 B).
// ---------------------------------------------------------------------------
#define SROW 72
#define QTILE 9216
#define KVTILE 4608
#define KVSTAGE 18432
#define FA_SMEM (55296 * 2)   // 110592 B

__global__ __launch_bounds__(256, 1) void flash_attn_mma(
    const __nv_bfloat16* __restrict__ Qh_g, const __nv_bfloat16* __restrict__ Ql_g,
    const __nv_bfloat16* __restrict__ Kh_g, const __nv_bfloat16* __restrict__ Kl_g,
    const __nv_bfloat16* __restrict__ Vh_g, const __nv_bfloat16* __restrict__ Vl_g,
    __nv_bfloat16* __restrict__ Oh_g, __nv_bfloat16* __restrict__ Ol_g)
{
    __nv_bfloat16* sm = (__nv_bfloat16*)dyn_smem;
    const uint32_t smb = smem_u32(sm);

    const int tid  = threadIdx.x;
    const int wid  = tid >> 5;
    const int lane = tid & 31;
    const int qb = (int)gridDim.x - 1 - (int)blockIdx.x;  // heavy first
    const int hh = blockIdx.y;
    const int q0 = qb * 128;
    const int kvoff = (hh >> 2) * HD;

    const __nv_bfloat16* kvsrc[4] = { Kh_g, Kl_g, Vh_g, Vl_g };

    auto issue_kv = [&](int jb) {
        const int k0 = jb * 64;
        const uint32_t sb = smb + (uint32_t)(KVSTAGE + (jb & 1) * KVSTAGE) * 2;
#pragma unroll
        for (int p = 0; p < 8; p++) {
            int idx = tid + p * 256;
            int t = idx >> 9;
            int rem = idx & 511;
            int r = rem >> 3;
            int c = rem & 7;
            cp16(sb + (uint32_t)(t * KVTILE + r * SROW + c * 8) * 2,
                 kvsrc[t] + (size_t)(k0 + r) * KV_W + kvoff + c * 8);
        }
        asm volatile("cp.async.commit_group;" ::: "memory");
    };

    // Q tiles (plain loads; consumed after first __syncthreads)
#pragma unroll
    for (int p = 0; p < 8; p++) {
        int idx = tid + p * 256;
        int t = idx >> 10;
        int rem = idx & 1023;
        int r = rem >> 3;
        int c = rem & 7;
        const __nv_bfloat16* src = (t ? Ql_g : Qh_g) +
            (size_t)(q0 + r) * HIDDEN + hh * HD + c * 8;
        uint4 d = *(const uint4*)src;
        *(uint4*)(sm + (t ? QTILE : 0) + r * SROW + c * 8) = d;
    }

    float o[8][4];
#pragma unroll
    for (int nt = 0; nt < 8; nt++)
#pragma unroll
        for (int e = 0; e < 4; e++) o[nt][e] = 0.f;
    float m0 = -1e30f, m1 = -1e30f, l0 = 0.f, l1 = 0.f;

    const int cr = lane >> 2;
    const int cc = (lane & 3) * 2;
    const int row0 = q0 + wid * 16 + cr;
    const int row1 = row0 + 8;

    const uint32_t aHq = smb + (uint32_t)(
        (wid * 16 + (lane & 15)) * SROW + ((lane >> 4) & 1) * 8) * 2;
    const uint32_t aLq = aHq + (uint32_t)QTILE * 2;
    const uint32_t bKoff = (uint32_t)((lane & 7) * SROW + ((lane >> 3) & 1) * 8) * 2;
    const uint32_t bVoff = (uint32_t)(((lane & 7) + ((lane >> 3) & 1) * 8) * SROW) * 2;

    const int nkv = 2 * qb + 2;
    issue_kv(0);
    issue_kv(1);

    for (int jb = 0; jb < nkv; jb++) {
        const int k0 = jb * 64;
        if (jb + 1 < nkv)
            asm volatile("cp.async.wait_group 1;" ::: "memory");
        else
            asm volatile("cp.async.wait_group 0;" ::: "memory");
        __syncthreads();

        const uint32_t stb = smb + (uint32_t)(KVSTAGE + (jb & 1) * KVSTAGE) * 2;
        const uint32_t bK = stb + bKoff;
        const uint32_t bV = stb + (uint32_t)(2 * KVTILE) * 2 + bVoff;

        // ---- S = Q K^T (3-term split) ----
        float s[8][4];
#pragma unroll
        for (int nt = 0; nt < 8; nt++)
#pragma unroll
            for (int e = 0; e < 4; e++) s[nt][e] = 0.f;

#pragma unroll
        for (int ks = 0; ks < 4; ks++) {
            uint32_t aH[4], aL[4];
            ldm_x4(aH, aHq + ks * 32);
            ldm_x4(aL, aLq + ks * 32);
#pragma unroll
            for (int nt = 0; nt < 8; nt++) {
                uint32_t bh[2], bl[2];
                uint32_t ba = bK + (uint32_t)(nt * 8 * SROW) * 2 + ks * 32;
                ldm_x2(bh, ba);
                ldm_x2(bl, ba + (uint32_t)KVTILE * 2);
                mma_bf16(s[nt], aH, bh);
                mma_bf16(s[nt], aL, bh);
                mma_bf16(s[nt], aH, bl);
            }
        }

        // ---- scale + causal mask ----
        const bool need_mask = (k0 + 63 > q0);
#pragma unroll
        for (int nt = 0; nt < 8; nt++) {
            int col = k0 + nt * 8 + cc;
            s[nt][0] *= 0.125f; s[nt][1] *= 0.125f;
            s[nt][2] *= 0.125f; s[nt][3] *= 0.125f;
            if (need_mask) {
                if (col > row0)     s[nt][0] = -1e30f;
                if (col + 1 > row0) s[nt][1] = -1e30f;
                if (col > row1)     s[nt][2] = -1e30f;
                if (col + 1 > row1) s[nt][3] = -1e30f;
            }
        }

        // ---- online softmax ----
        float mx0 = -1e30f, mx1 = -1e30f;
#pragma unroll
        for (int nt = 0; nt < 8; nt++) {
            mx0 = fmaxf(mx0, fmaxf(s[nt][0], s[nt][1]));
            mx1 = fmaxf(mx1, fmaxf(s[nt][2], s[nt][3]));
        }
        mx0 = fmaxf(mx0, __shfl_xor_sync(0xffffffffu, mx0, 1));
        mx0 = fmaxf(mx0, __shfl_xor_sync(0xffffffffu, mx0, 2));
        mx1 = fmaxf(mx1, __shfl_xor_sync(0xffffffffu, mx1, 1));
        mx1 = fmaxf(mx1, __shfl_xor_sync(0xffffffffu, mx1, 2));

        float m0n = fmaxf(m0, mx0);
        float m1n = fmaxf(m1, mx1);

        float sum0 = 0.f, sum1 = 0.f;
#pragma unroll
        for (int nt = 0; nt < 8; nt++) {
            s[nt][0] = __expf(s[nt][0] - m0n);
            s[nt][1] = __expf(s[nt][1] - m0n);
            s[nt][2] = __expf(s[nt][2] - m1n);
            s[nt][3] = __expf(s[nt][3] - m1n);
            sum0 += s[nt][0] + s[nt][1];
            sum1 += s[nt][2] + s[nt][3];
        }
        sum0 += __shfl_xor_sync(0xffffffffu, sum0, 1);
        sum0 += __shfl_xor_sync(0xffffffffu, sum0, 2);
        sum1 += __shfl_xor_sync(0xffffffffu, sum1, 1);
        sum1 += __shfl_xor_sync(0xffffffffu, sum1, 2);

        float sc0 = __expf(m0 - m0n);
        float sc1 = __expf(m1 - m1n);
        l0 = l0 * sc0 + sum0;
        l1 = l1 * sc1 + sum1;
        m0 = m0n; m1 = m1n;

#pragma unroll
        for (int nt = 0; nt < 8; nt++) {
            o[nt][0] *= sc0; o[nt][1] *= sc0;
            o[nt][2] *= sc1; o[nt][3] *= sc1;
        }

        // ---- P V (3-term split) ----
#pragma unroll
        for (int ks = 0; ks < 4; ks++) {
            uint32_t aP[4], aPl[4];
#pragma unroll
            for (int half = 0; half < 2; half++) {
                int nt = 2 * ks + half;
#pragma unroll
                for (int rr = 0; rr < 2; rr++) {
                    float e0 = s[nt][rr * 2 + 0];
                    float e1 = s[nt][rr * 2 + 1];
                    __nv_bfloat16 h0 = __float2bfloat16(e0);
                    __nv_bfloat16 h1 = __float2bfloat16(e1);
                    float r0f = e0 - __bfloat162float(h0);
                    float r1f = e1 - __bfloat162float(h1);
                    __nv_bfloat162 hp = __halves2bfloat162(h0, h1);
                    __nv_bfloat162 lp = __halves2bfloat162(
                        __float2bfloat16(r0f), __float2bfloat16(r1f));
                    aP [half * 2 + rr] = *reinterpret_cast<uint32_t*>(&hp);
                    aPl[half * 2 + rr] = *reinterpret_cast<uint32_t*>(&lp);
                }
            }
#pragma unroll
            for (int nt = 0; nt < 8; nt++) {
                uint32_t bh[2], bl[2];
                uint32_t ba = bV + (uint32_t)(ks * 16 * SROW + nt * 8) * 2;
                ldm_x2t(bh, ba);
                ldm_x2t(bl, ba + (uint32_t)KVTILE * 2);
                mma_bf16(o[nt], aP,  bh);
                mma_bf16(o[nt], aPl, bh);
                mma_bf16(o[nt], aP,  bl);
            }
        }

        __syncthreads();                 // stage jb fully consumed
        if (jb + 2 < nkv) issue_kv(jb + 2);
    }

    // ---- normalize + store bf16 hi/lo ----
    float inv0 = 1.f / l0;
    float inv1 = 1.f / l1;
#pragma unroll
    for (int nt = 0; nt < 8; nt++) {
        size_t i0 = (size_t)row0 * HIDDEN + hh * HD + nt * 8 + cc;
        size_t i1 = (size_t)row1 * HIDDEN + hh * HD + nt * 8 + cc;
        float e0 = o[nt][0] * inv0, e1 = o[nt][1] * inv0;
        float e2 = o[nt][2] * inv1, e3 = o[nt][3] * inv1;
        __nv_bfloat16 h0 = __float2bfloat16(e0), h1 = __float2bfloat16(e1);
        __nv_bfloat16 h2 = __float2bfloat16(e2), h3 = __float2bfloat16(e3);
        __nv_bfloat162 hp0 = __halves2bfloat162(h0, h1);
        __nv_bfloat162 hp1 = __halves2bfloat162(h2, h3);
        __nv_bfloat162 lp0 = __halves2bfloat162(
            __float2bfloat16(e0 - __bfloat162float(h0)),
            __float2bfloat16(e1 - __bfloat162float(h1)));
        __nv_bfloat162 lp1 = __halves2bfloat162(
            __float2bfloat16(e2 - __bfloat162float(h2)),
            __float2bfloat16(e3 - __bfloat162float(h3)));
        *(uint32_t*)(Oh_g + i0) = *reinterpret_cast<uint32_t*>(&hp0);
        *(uint32_t*)(Oh_g + i1) = *reinterpret_cast<uint32_t*>(&hp1);
        *(uint32_t*)(Ol_g + i0) = *reinterpret_cast<uint32_t*>(&lp0);
        *(uint32_t*)(Ol_g + i1) = *reinterpret_cast<uint32_t*>(&lp1);
    }
}

// ---------------------------------------------------------------------------
// kernel_launch
// ---------------------------------------------------------------------------
extern "C" void kernel_launch(void* const* d_in, const int* in_sizes, int n_in,
                              void* d_out, int out_size)
{
    const float* X  = (const float*)d_in[0];
    const float* Wq = (const float*)d_in[2];
    const float* Wk = (const float*)d_in[3];
    const float* Wv = (const float*)d_in[4];
    const float* Wo = (const float*)d_in[5];
    float* out = (float*)d_out;

    __nv_bfloat16 *Xh, *Xl, *Wqh, *Wql, *Wkh, *Wkl, *Wvh, *Wvl, *Woh, *Wol;
    __nv_bfloat16 *qh, *ql, *kh, *kl, *vh, *vl, *Ath, *Atl;
    cudaGetSymbolAddress((void**)&Xh, g_Xh);   cudaGetSymbolAddress((void**)&Xl, g_Xl);
    cudaGetSymbolAddress((void**)&Wqh, g_Wqh); cudaGetSymbolAddress((void**)&Wql, g_Wql);
    cudaGetSymbolAddress((void**)&Wkh, g_Wkh); cudaGetSymbolAddress((void**)&Wkl, g_Wkl);
    cudaGetSymbolAddress((void**)&Wvh, g_Wvh); cudaGetSymbolAddress((void**)&Wvl, g_Wvl);
    cudaGetSymbolAddress((void**)&Woh, g_Woh); cudaGetSymbolAddress((void**)&Wol, g_Wol);
    cudaGetSymbolAddress((void**)&qh, g_qh);   cudaGetSymbolAddress((void**)&ql, g_ql);
    cudaGetSymbolAddress((void**)&kh, g_kh);   cudaGetSymbolAddress((void**)&kl, g_kl);
    cudaGetSymbolAddress((void**)&vh, g_vh);   cudaGetSymbolAddress((void**)&vl, g_vl);
    cudaGetSymbolAddress((void**)&Ath, g_Ath); cudaGetSymbolAddress((void**)&Atl, g_Atl);

    cvt_split<<<(S_LEN * HIDDEN) / 1024, 256>>>(X, Xh, Xl, S_LEN * HIDDEN);
    cvt_split<<<(HIDDEN * HIDDEN) / 1024, 256>>>(Wq, Wqh, Wql, HIDDEN * HIDDEN);
    cvt_split<<<(KV_W * HIDDEN) / 1024, 256>>>(Wk, Wkh, Wkl, KV_W * HIDDEN);
    cvt_split<<<(KV_W * HIDDEN) / 1024, 256>>>(Wv, Wvh, Wvl, KV_W * HIDDEN);
    cvt_split<<<(HIDDEN * HIDDEN) / 1024, 256>>>(Wo, Woh, Wol, HIDDEN * HIDDEN);

    cudaFuncSetAttribute(gemm_qkv, cudaFuncAttributeMaxDynamicSharedMemorySize, GEMM_SMEM);
    cudaFuncSetAttribute(gemm_oproj, cudaFuncAttributeMaxDynamicSharedMemorySize, GEMM_SMEM);

    gemm_qkv<<<dim3(24, 16), 256, GEMM_SMEM>>>();

    cudaFuncSetAttribute(flash_attn_mma, cudaFuncAttributeMaxDynamicSharedMemorySize, FA_SMEM);
    flash_attn_mma<<<dim3(S_LEN / 128, NH), 256, FA_SMEM>>>(
        qh, ql, kh, kl, vh, vl, Ath, Atl);

    gemm_oproj<<<dim3(16, 16), 256, GEMM_SMEM>>>(out);
}

// round 11
// speedup vs baseline: 1.0944x; 1.0551x over previous
#include <cuda_runtime.h>
#include <cuda_bf16.h>
#include <math.h>
#include <stdint.h>

#define S_LEN 2048
#define HIDDEN 2048
#define NH 32
#define NKV 8
#define HD 64
#define KV_W (NKV*HD)   // 512

// Q pre-scale: 1/sqrt(64) * log2(e)  (softmax done in base-2 domain)
#define QSCALE 0.18033688011112042f

// ---------------------------------------------------------------------------
// Device-global scratch
// ---------------------------------------------------------------------------
__device__ __nv_bfloat16 g_Xh[S_LEN * HIDDEN],   g_Xl[S_LEN * HIDDEN];
__device__ __nv_bfloat16 g_Wqh[HIDDEN * HIDDEN], g_Wql[HIDDEN * HIDDEN];
__device__ __nv_bfloat16 g_Wkh[KV_W * HIDDEN],   g_Wkl[KV_W * HIDDEN];
__device__ __nv_bfloat16 g_Wvh[KV_W * HIDDEN],   g_Wvl[KV_W * HIDDEN];
__device__ __nv_bfloat16 g_Woh[HIDDEN * HIDDEN], g_Wol[HIDDEN * HIDDEN];

__device__ __nv_bfloat16 g_qh[S_LEN * HIDDEN], g_ql[S_LEN * HIDDEN];
__device__ __nv_bfloat16 g_kh[S_LEN * KV_W],   g_kl[S_LEN * KV_W];
__device__ __nv_bfloat16 g_vh[S_LEN * KV_W],   g_vl[S_LEN * KV_W];
__device__ __nv_bfloat16 g_Ath[S_LEN * HIDDEN], g_Atl[S_LEN * HIDDEN];

// ---------------------------------------------------------------------------
// helpers
// ---------------------------------------------------------------------------
__device__ __forceinline__ uint32_t smem_u32(const void* p) {
    uint32_t a;
    asm("{ .reg .u64 t; cvta.to.shared.u64 t, %1; cvt.u32.u64 %0, t; }"
        : "=r"(a) : "l"(p));
    return a;
}
__device__ __forceinline__ void ldm_x4(uint32_t* r, uint32_t addr) {
    asm volatile("ldmatrix.sync.aligned.m8n8.x4.shared.b16 {%0,%1,%2,%3}, [%4];"
                 : "=r"(r[0]), "=r"(r[1]), "=r"(r[2]), "=r"(r[3]) : "r"(addr));
}
__device__ __forceinline__ void ldm_x2(uint32_t* r, uint32_t addr) {
    asm volatile("ldmatrix.sync.aligned.m8n8.x2.shared.b16 {%0,%1}, [%2];"
                 : "=r"(r[0]), "=r"(r[1]) : "r"(addr));
}
__device__ __forceinline__ void ldm_x2t(uint32_t* r, uint32_t addr) {
    asm volatile("ldmatrix.sync.aligned.m8n8.x2.trans.shared.b16 {%0,%1}, [%2];"
                 : "=r"(r[0]), "=r"(r[1]) : "r"(addr));
}
__device__ __forceinline__ void mma_bf16(float* d, const uint32_t* a, const uint32_t* b) {
    asm volatile(
        "mma.sync.aligned.m16n8k16.row.col.f32.bf16.bf16.f32 "
        "{%0,%1,%2,%3}, {%4,%5,%6,%7}, {%8,%9}, {%0,%1,%2,%3};"
        : "+f"(d[0]), "+f"(d[1]), "+f"(d[2]), "+f"(d[3])
        : "r"(a[0]), "r"(a[1]), "r"(a[2]), "r"(a[3]), "r"(b[0]), "r"(b[1]));
}
__device__ __forceinline__ void cp16(uint32_t saddr, const void* g) {
    asm volatile("cp.async.cg.shared.global [%0], [%1], 16;"
                 :: "r"(saddr), "l"(g) : "memory");
}
__device__ __forceinline__ float ex2(float x) {
    float r;
    asm("ex2.approx.ftz.f32 %0, %1;" : "=f"(r) : "f"(x));
    return r;
}
// split a float pair into packed bf16 hi + packed bf16 residual
__device__ __forceinline__ void split2(float e0, float e1,
                                       uint32_t& hp_u, uint32_t& lp_u) {
    __nv_bfloat162 hp = __float22bfloat162_rn(make_float2(e0, e1));
    float h0 = __low2float(hp), h1 = __high2float(hp);
    __nv_bfloat162 lp = __float22bfloat162_rn(make_float2(e0 - h0, e1 - h1));
    hp_u = *reinterpret_cast<uint32_t*>(&hp);
    lp_u = *reinterpret_cast<uint32_t*>(&lp);
}

// ---------------------------------------------------------------------------
// Fused fp32 -> bf16 hi/lo split for all 5 tensors (one launch).
// Segments in units of 1024 elems/block:
//   X 4096 | Wq 4096 | Wk 1024 | Wv 1024 | Wo 4096  => 14336 blocks
// ---------------------------------------------------------------------------
__global__ __launch_bounds__(256) void cvt_all(
    const float* __restrict__ X,  const float* __restrict__ Wq,
    const float* __restrict__ Wk, const float* __restrict__ Wv,
    const float* __restrict__ Wo)
{
    int b = blockIdx.x;
    const float* src;
    __nv_bfloat16 *hi, *lo;
    int base;
    if (b < 4096)       { src = X;  hi = g_Xh;  lo = g_Xl;  base = b; }
    else if (b < 8192)  { src = Wq; hi = g_Wqh; lo = g_Wql; base = b - 4096; }
    else if (b < 9216)  { src = Wk; hi = g_Wkh; lo = g_Wkl; base = b - 8192; }
    else if (b < 10240) { src = Wv; hi = g_Wvh; lo = g_Wvl; base = b - 9216; }
    else                { src = Wo; hi = g_Woh; lo = g_Wol; base = b - 10240; }

    int i = (base * 256 + threadIdx.x) * 4;
    float4 v = *(const float4*)(src + i);
    uint32_t h01, l01, h23, l23;
    split2(v.x, v.y, h01, l01);
    split2(v.z, v.w, h23, l23);
    uint32_t* hp = (uint32_t*)(hi + i);
    uint32_t* lp = (uint32_t*)(lo + i);
    hp[0] = h01; hp[1] = h23;
    lp[0] = l01; lp[1] = l23;
}

// ---------------------------------------------------------------------------
// Pipelined GEMM mainloop (R7 config): BK=64, 3-stage cp.async, SW128 XOR.
// ---------------------------------------------------------------------------
#define TILEB 16384
#define STAGEB 65536
#define GEMM_SMEM (3 * STAGEB)

extern __shared__ char dyn_smem[];

__device__ __forceinline__ void gemm_core(
    const __nv_bfloat16* __restrict__ gA0, const __nv_bfloat16* __restrict__ gA1,
    const __nv_bfloat16* __restrict__ gB0, const __nv_bfloat16* __restrict__ gB1,
    int K, uint32_t smb, float (&acc)[4][4][4])
{
    const int tid = threadIdx.x;
    const int wid = tid >> 5;
    const int lane = tid & 31;
    const int wm = wid >> 2;
    const int wn = wid & 3;

    const __nv_bfloat16* gT[4] = { gA0, gA1, gB0, gB1 };
    const int ldRow = tid >> 3;
    const int ldC   = tid & 7;
    const int nk = K / 64;

    auto issue = [&](int kc, int stg) {
        uint32_t sb = smb + stg * STAGEB;
#pragma unroll
        for (int t = 0; t < 4; t++) {
#pragma unroll
            for (int p = 0; p < 4; p++) {
                int row = ldRow + p * 32;
                int sw = ldC ^ (row & 7);
                cp16(sb + t * TILEB + row * 128 + sw * 16,
                     gT[t] + (size_t)row * K + kc * 64 + ldC * 8);
            }
        }
        asm volatile("cp.async.commit_group;" ::: "memory");
    };

    issue(0, 0);
    issue(1, 1);

    for (int kc = 0; kc < nk; kc++) {
        if (kc + 1 < nk)
            asm volatile("cp.async.wait_group 1;" ::: "memory");
        else
            asm volatile("cp.async.wait_group 0;" ::: "memory");
        __syncthreads();
        if (kc + 2 < nk) issue(kc + 2, (kc + 2) % 3);

        const uint32_t sb = smb + (kc % 3) * STAGEB;
#pragma unroll
        for (int ks = 0; ks < 4; ks++) {
            uint32_t bH[4][2], bL[4][2];
#pragma unroll
            for (int nt = 0; nt < 4; nt++) {
                int row = wn * 32 + nt * 8 + (lane & 7);
                int ch = ks * 2 + ((lane >> 3) & 1);
                uint32_t ba = sb + 2 * TILEB + row * 128 + ((ch ^ (row & 7)) * 16);
                ldm_x2(bH[nt], ba);
                ldm_x2(bL[nt], ba + TILEB);
            }
#pragma unroll
            for (int mt = 0; mt < 4; mt++) {
                int row = wm * 64 + mt * 16 + (lane & 15);
                int ch = ks * 2 + ((lane >> 4) & 1);
                uint32_t aa = sb + row * 128 + ((ch ^ (row & 7)) * 16);
                uint32_t aH[4], aL[4];
                ldm_x4(aH, aa);
                ldm_x4(aL, aa + TILEB);
#pragma unroll
                for (int nt = 0; nt < 4; nt++) mma_bf16(acc[mt][nt], aH, bH[nt]);
#pragma unroll
                for (int nt = 0; nt < 4; nt++) mma_bf16(acc[mt][nt], aL, bH[nt]);
#pragma unroll
                for (int nt = 0; nt < 4; nt++) mma_bf16(acc[mt][nt], aH, bL[nt]);
            }
        }
    }
}

__device__ __forceinline__ void epi_split(
    float (&acc)[4][4][4], __nv_bfloat16* Ch, __nv_bfloat16* Cl,
    int r0, int c0, int N, float scale)
{
    const int lane = threadIdx.x & 31;
    const int wid = threadIdx.x >> 5;
    const int wm = wid >> 2, wn = wid & 3;
    const int cr = lane >> 2;
    const int cc = (lane & 3) * 2;
#pragma unroll
    for (int mt = 0; mt < 4; mt++) {
#pragma unroll
        for (int nt = 0; nt < 4; nt++) {
            size_t i0 = (size_t)(r0 + wm * 64 + mt * 16 + cr) * N
                      + c0 + wn * 32 + nt * 8 + cc;
            size_t i1 = i0 + 8 * (size_t)N;
#pragma unroll
            for (int half = 0; half < 2; half++) {
                size_t ix = half ? i1 : i0;
                float e0 = acc[mt][nt][half * 2 + 0] * scale;
                float e1 = acc[mt][nt][half * 2 + 1] * scale;
                uint32_t hp, lp;
                split2(e0, e1, hp, lp);
                *(uint32_t*)(Ch + ix) = hp;
                *(uint32_t*)(Cl + ix) = lp;
            }
        }
    }
}

__global__ __launch_bounds__(256, 1) void gemm_qkv()
{
    const uint32_t smb = smem_u32(dyn_smem);
    const int bx = blockIdx.x;
    const int r0 = blockIdx.y * 128;

    const __nv_bfloat16 *Bh, *Bl;
    __nv_bfloat16 *Ch, *Cl;
    int N, c0;
    float scale;
    if (bx < 16)      { Bh = g_Wqh; Bl = g_Wql; Ch = g_qh; Cl = g_ql; N = HIDDEN; c0 = bx * 128;       scale = QSCALE; }
    else if (bx < 20) { Bh = g_Wkh; Bl = g_Wkl; Ch = g_kh; Cl = g_kl; N = KV_W;  c0 = (bx - 16) * 128; scale = 1.f; }
    else              { Bh = g_Wvh; Bl = g_Wvl; Ch = g_vh; Cl = g_vl; N = KV_W;  c0 = (bx - 20) * 128; scale = 1.f; }

    float acc[4][4][4];
#pragma unroll
    for (int i = 0; i < 4; i++)
#pragma unroll
        for (int j = 0; j < 4; j++)
#pragma unroll
            for (int e = 0; e < 4; e++) acc[i][j][e] = 0.f;

    gemm_core(g_Xh + (size_t)r0 * HIDDEN, g_Xl + (size_t)r0 * HIDDEN,
              Bh + (size_t)c0 * HIDDEN, Bl + (size_t)c0 * HIDDEN,
              HIDDEN, smb, acc);
    epi_split(acc, Ch, Cl, r0, c0, N, scale);
}

__global__ __launch_bounds__(256, 1) void gemm_oproj(float* __restrict__ Cf)
{
    const uint32_t smb = smem_u32(dyn_smem);
    const int r0 = blockIdx.y * 128;
    const int c0 = blockIdx.x * 128;

    float acc[4][4][4];
#pragma unroll
    for (int i = 0; i < 4; i++)
#pragma unroll
        for (int j = 0; j < 4; j++)
#pragma unroll
            for (int e = 0; e < 4; e++) acc[i][j][e] = 0.f;

    gemm_core(g_Ath + (size_t)r0 * HIDDEN, g_Atl + (size_t)r0 * HIDDEN,
              g_Woh + (size_t)c0 * HIDDEN, g_Wol + (size_t)c0 * HIDDEN,
              HIDDEN, smb, acc);

    const int lane = threadIdx.x & 31;
    const int wid = threadIdx.x >> 5;
    const int wm = wid >> 2, wn = wid & 3;
    const int cr = lane >> 2;
    const int cc = (lane & 3) * 2;
#pragma unroll
    for (int mt = 0; mt < 4; mt++) {
#pragma unroll
        for (int nt = 0; nt < 4; nt++) {
            float* base = Cf + (size_t)(r0 + wm * 64 + mt * 16 + cr) * HIDDEN
                             + c0 + wn * 32 + nt * 8 + cc;
            *(float2*)base = make_float2(acc[mt][nt][0], acc[mt][nt][1]);
            *(float2*)(base + 8 * (size_t)HIDDEN) =
                make_float2(acc[mt][nt][2], acc[mt][nt][3]);
        }
    }
}

// ---------------------------------------------------------------------------
// Flash attention, cp.async K/V (R10 pipeline), base-2 softmax with
// pre-scaled Q (no per-element scale multiply; exp = single MUFU).
// ---------------------------------------------------------------------------
#define SROW 72
#define QTILE 9216
#define KVTILE 4608
#define KVSTAGE 18432
#define FA_SMEM (55296 * 2)

__global__ __launch_bounds__(256, 1) void flash_attn_mma(
    const __nv_bfloat16* __restrict__ Qh_g, const __nv_bfloat16* __restrict__ Ql_g,
    const __nv_bfloat16* __restrict__ Kh_g, const __nv_bfloat16* __restrict__ Kl_g,
    const __nv_bfloat16* __restrict__ Vh_g, const __nv_bfloat16* __restrict__ Vl_g,
    __nv_bfloat16* __restrict__ Oh_g, __nv_bfloat16* __restrict__ Ol_g)
{
    __nv_bfloat16* sm = (__nv_bfloat16*)dyn_smem;
    const uint32_t smb = smem_u32(sm);

    const int tid  = threadIdx.x;
    const int wid  = tid >> 5;
    const int lane = tid & 31;
    const int qb = (int)gridDim.x - 1 - (int)blockIdx.x;
    const int hh = blockIdx.y;
    const int q0 = qb * 128;
    const int kvoff = (hh >> 2) * HD;

    const __nv_bfloat16* kvsrc[4] = { Kh_g, Kl_g, Vh_g, Vl_g };

    auto issue_kv = [&](int jb) {
        const int k0 = jb * 64;
        const uint32_t sb = smb + (uint32_t)(KVSTAGE + (jb & 1) * KVSTAGE) * 2;
#pragma unroll
        for (int p = 0; p < 8; p++) {
            int idx = tid + p * 256;
            int t = idx >> 9;
            int rem = idx & 511;
            int r = rem >> 3;
            int c = rem & 7;
            cp16(sb + (uint32_t)(t * KVTILE + r * SROW + c * 8) * 2,
                 kvsrc[t] + (size_t)(k0 + r) * KV_W + kvoff + c * 8);
        }
        asm volatile("cp.async.commit_group;" ::: "memory");
    };

#pragma unroll
    for (int p = 0; p < 8; p++) {
        int idx = tid + p * 256;
        int t = idx >> 10;
        int rem = idx & 1023;
        int r = rem >> 3;
        int c = rem & 7;
        const __nv_bfloat16* src = (t ? Ql_g : Qh_g) +
            (size_t)(q0 + r) * HIDDEN + hh * HD + c * 8;
        uint4 d = *(const uint4*)src;
        *(uint4*)(sm + (t ? QTILE : 0) + r * SROW + c * 8) = d;
    }

    float o[8][4];
#pragma unroll
    for (int nt = 0; nt < 8; nt++)
#pragma unroll
        for (int e = 0; e < 4; e++) o[nt][e] = 0.f;
    float m0 = -1e30f, m1 = -1e30f, l0 = 0.f, l1 = 0.f;

    const int cr = lane >> 2;
    const int cc = (lane & 3) * 2;
    const int row0 = q0 + wid * 16 + cr;
    const int row1 = row0 + 8;

    const uint32_t aHq = smb + (uint32_t)(
        (wid * 16 + (lane & 15)) * SROW + ((lane >> 4) & 1) * 8) * 2;
    const uint32_t aLq = aHq + (uint32_t)QTILE * 2;
    const uint32_t bKoff = (uint32_t)((lane & 7) * SROW + ((lane >> 3) & 1) * 8) * 2;
    const uint32_t bVoff = (uint32_t)(((lane & 7) + ((lane >> 3) & 1) * 8) * SROW) * 2;

    const int nkv = 2 * qb + 2;
    issue_kv(0);
    issue_kv(1);

    for (int jb = 0; jb < nkv; jb++) {
        const int k0 = jb * 64;
        if (jb + 1 < nkv)
            asm volatile("cp.async.wait_group 1;" ::: "memory");
        else
            asm volatile("cp.async.wait_group 0;" ::: "memory");
        __syncthreads();

        const uint32_t stb = smb + (uint32_t)(KVSTAGE + (jb & 1) * KVSTAGE) * 2;
        const uint32_t bK = stb + bKoff;
        const uint32_t bV = stb + (uint32_t)(2 * KVTILE) * 2 + bVoff;

        // ---- S = Q K^T (scores already in log2 domain via Q pre-scale) ----
        float s[8][4];
#pragma unroll
        for (int nt = 0; nt < 8; nt++)
#pragma unroll
            for (int e = 0; e < 4; e++) s[nt][e] = 0.f;

#pragma unroll
        for (int ks = 0; ks < 4; ks++) {
            uint32_t aH[4], aL[4];
            ldm_x4(aH, aHq + ks * 32);
            ldm_x4(aL, aLq + ks * 32);
#pragma unroll
            for (int nt = 0; nt < 8; nt++) {
                uint32_t bh[2], bl[2];
                uint32_t ba = bK + (uint32_t)(nt * 8 * SROW) * 2 + ks * 32;
                ldm_x2(bh, ba);
                ldm_x2(bl, ba + (uint32_t)KVTILE * 2);
                mma_bf16(s[nt], aH, bh);
                mma_bf16(s[nt], aL, bh);
                mma_bf16(s[nt], aH, bl);
            }
        }

        // ---- causal mask only (no scale needed) ----
        if (k0 + 63 > q0) {
#pragma unroll
            for (int nt = 0; nt < 8; nt++) {
                int col = k0 + nt * 8 + cc;
                if (col > row0)     s[nt][0] = -1e30f;
                if (col + 1 > row0) s[nt][1] = -1e30f;
                if (col > row1)     s[nt][2] = -1e30f;
                if (col + 1 > row1) s[nt][3] = -1e30f;
            }
        }

        // ---- online softmax (base-2) ----
        float mx0 = -1e30f, mx1 = -1e30f;
#pragma unroll
        for (int nt = 0; nt < 8; nt++) {
            mx0 = fmaxf(mx0, fmaxf(s[nt][0], s[nt][1]));
            mx1 = fmaxf(mx1, fmaxf(s[nt][2], s[nt][3]));
        }
        mx0 = fmaxf(mx0, __shfl_xor_sync(0xffffffffu, mx0, 1));
        mx0 = fmaxf(mx0, __shfl_xor_sync(0xffffffffu, mx0, 2));
        mx1 = fmaxf(mx1, __shfl_xor_sync(0xffffffffu, mx1, 1));
        mx1 = fmaxf(mx1, __shfl_xor_sync(0xffffffffu, mx1, 2));

        float m0n = fmaxf(m0, mx0);
        float m1n = fmaxf(m1, mx1);

        float sum0 = 0.f, sum1 = 0.f;
#pragma unroll
        for (int nt = 0; nt < 8; nt++) {
            s[nt][0] = ex2(s[nt][0] - m0n);
            s[nt][1] = ex2(s[nt][1] - m0n);
            s[nt][2] = ex2(s[nt][2] - m1n);
            s[nt][3] = ex2(s[nt][3] - m1n);
            sum0 += s[nt][0] + s[nt][1];
            sum1 += s[nt][2] + s[nt][3];
        }
        sum0 += __shfl_xor_sync(0xffffffffu, sum0, 1);
        sum0 += __shfl_xor_sync(0xffffffffu, sum0, 2);
        sum1 += __shfl_xor_sync(0xffffffffu, sum1, 1);
        sum1 += __shfl_xor_sync(0xffffffffu, sum1, 2);

        float sc0 = ex2(m0 - m0n);
        float sc1 = ex2(m1 - m1n);
        l0 = l0 * sc0 + sum0;
        l1 = l1 * sc1 + sum1;
        m0 = m0n; m1 = m1n;

#pragma unroll
        for (int nt = 0; nt < 8; nt++) {
            o[nt][0] *= sc0; o[nt][1] *= sc0;
            o[nt][2] *= sc1; o[nt][3] *= sc1;
        }

        // ---- P V (3-term split) ----
#pragma unroll
        for (int ks = 0; ks < 4; ks++) {
            uint32_t aP[4], aPl[4];
#pragma unroll
            for (int half = 0; half < 2; half++) {
                int nt = 2 * ks + half;
                split2(s[nt][0], s[nt][1], aP[half * 2 + 0], aPl[half * 2 + 0]);
                split2(s[nt][2], s[nt][3], aP[half * 2 + 1], aPl[half * 2 + 1]);
            }
#pragma unroll
            for (int nt = 0; nt < 8; nt++) {
                uint32_t bh[2], bl[2];
                uint32_t ba = bV + (uint32_t)(ks * 16 * SROW + nt * 8) * 2;
                ldm_x2t(bh, ba);
                ldm_x2t(bl, ba + (uint32_t)KVTILE * 2);
                mma_bf16(o[nt], aP,  bh);
                mma_bf16(o[nt], aPl, bh);
                mma_bf16(o[nt], aP,  bl);
            }
        }

        __syncthreads();
        if (jb + 2 < nkv) issue_kv(jb + 2);
    }

    // ---- normalize + store bf16 hi/lo ----
    float inv0 = 1.f / l0;
    float inv1 = 1.f / l1;
#pragma unroll
    for (int nt = 0; nt < 8; nt++) {
        size_t i0 = (size_t)row0 * HIDDEN + hh * HD + nt * 8 + cc;
        size_t i1 = (size_t)row1 * HIDDEN + hh * HD + nt * 8 + cc;
        uint32_t hp0, lp0, hp1, lp1;
        split2(o[nt][0] * inv0, o[nt][1] * inv0, hp0, lp0);
        split2(o[nt][2] * inv1, o[nt][3] * inv1, hp1, lp1);
        *(uint32_t*)(Oh_g + i0) = hp0;
        *(uint32_t*)(Oh_g + i1) = hp1;
        *(uint32_t*)(Ol_g + i0) = lp0;
        *(uint32_t*)(Ol_g + i1) = lp1;
    }
}

// ---------------------------------------------------------------------------
// kernel_launch
// ---------------------------------------------------------------------------
extern "C" void kernel_launch(void* const* d_in, const int* in_sizes, int n_in,
                              void* d_out, int out_size)
{
    const float* X  = (const float*)d_in[0];
    const float* Wq = (const float*)d_in[2];
    const float* Wk = (const float*)d_in[3];
    const float* Wv = (const float*)d_in[4];
    const float* Wo = (const float*)d_in[5];
    float* out = (float*)d_out;

    __nv_bfloat16 *qh, *ql, *kh, *kl, *vh, *vl, *Ath, *Atl;
    cudaGetSymbolAddress((void**)&qh, g_qh);   cudaGetSymbolAddress((void**)&ql, g_ql);
    cudaGetSymbolAddress((void**)&kh, g_kh);   cudaGetSymbolAddress((void**)&kl, g_kl);
    cudaGetSymbolAddress((void**)&vh, g_vh);   cudaGetSymbolAddress((void**)&vl, g_vl);
    cudaGetSymbolAddress((void**)&Ath, g_Ath); cudaGetSymbolAddress((void**)&Atl, g_Atl);

    // Fused conversion (all inputs + weights), single launch
    cvt_all<<<14336, 256>>>(X, Wq, Wk, Wv, Wo);

    cudaFuncSetAttribute(gemm_qkv, cudaFuncAttributeMaxDynamicSharedMemorySize, GEMM_SMEM);
    cudaFuncSetAttribute(gemm_oproj, cudaFuncAttributeMaxDynamicSharedMemorySize, GEMM_SMEM);

    gemm_qkv<<<dim3(24, 16), 256, GEMM_SMEM>>>();

    cudaFuncSetAttribute(flash_attn_mma, cudaFuncAttributeMaxDynamicSharedMemorySize, FA_SMEM);
    flash_attn_mma<<<dim3(S_LEN / 128, NH), 256, FA_SMEM>>>(
        qh, ql, kh, kl, vh, vl, Ath, Atl);

    gemm_oproj<<<dim3(16, 16), 256, GEMM_SMEM>>>(out);
}